// round 3
// baseline (speedup 1.0000x reference)
#include <cuda_runtime.h>
#include <math.h>

// Problem constants (from reference)
#define NB    32      // spline bins
#define NFEAT 64      // conditioner input features
#define NH    256     // hidden width
#define NP    96      // 3*NB params per row
#define TILE  16      // rows per CTA
#define NT    256     // threads per CTA

#define TWO_PI_F   6.2831853071795864769f
#define MIN_WH     1e-3f
#define MIN_D      1e-3f
#define DERIV_OFF  0.5413248546129181f   // log(e-1)
#define SIZE_SCALE (1.0f - 1e-3f * 32.0f) // 0.968

__device__ __forceinline__ float softplus_f(float x) {
    // numerically stable softplus matching jax.nn.softplus
    return (x > 0.0f) ? (x + log1pf(expf(-x))) : log1pf(expf(x));
}

__global__ __launch_bounds__(NT)
void cyl_flow_kernel(const float* __restrict__ theta,
                     const float* __restrict__ xc,
                     const float* __restrict__ W1,
                     const float* __restrict__ b1,
                     const float* __restrict__ W2,
                     const float* __restrict__ b2,
                     const float* __restrict__ eta,
                     float* __restrict__ out,
                     int B)
{
    __shared__ float x_s[TILE][NFEAT];        // 4 KB
    __shared__ float h_s[TILE][NH + 1];       // ~16.4 KB (pad avoids bank conflicts)
    __shared__ float p_s[TILE][NP];           // 6 KB

    const int t    = threadIdx.x;
    const int row0 = blockIdx.x * TILE;

    // ---- load x tile (coalesced) ----
    #pragma unroll
    for (int i = t; i < TILE * NFEAT; i += NT) {
        int r = i >> 6, k = i & 63;
        int row = row0 + r;
        x_s[r][k] = (row < B) ? xc[row * NFEAT + k] : 0.0f;
    }
    __syncthreads();

    // ---- stage 1: h = relu(x @ W1 + b1); thread t owns hidden column t ----
    {
        float acc[TILE];
        #pragma unroll
        for (int r = 0; r < TILE; r++) acc[r] = 0.0f;

        const int c = t;
        #pragma unroll 4
        for (int k = 0; k < NFEAT; k++) {
            float w = W1[k * NH + c];          // coalesced, L1-resident (64KB)
            #pragma unroll
            for (int r = 0; r < TILE; r++)
                acc[r] = fmaf(x_s[r][k], w, acc[r]);   // x_s broadcast
        }
        float bb = b1[c];
        #pragma unroll
        for (int r = 0; r < TILE; r++)
            h_s[r][c] = fmaxf(acc[r] + bb, 0.0f);
    }
    __syncthreads();

    // ---- stage 2: params = (h @ W2 + b2) * eta ----
    // threads 0..95  -> cols 0..95, rows 0..7
    // threads 96..191-> cols 0..95, rows 8..15  (warp-aligned: smem reads broadcast)
    if (t < 192) {
        const int g     = t / 96;
        const int c     = t - g * 96;
        const int rbase = g * 8;
        float acc[8];
        #pragma unroll
        for (int rr = 0; rr < 8; rr++) acc[rr] = 0.0f;

        #pragma unroll 2
        for (int k = 0; k < NH; k++) {
            float w = W2[k * NP + c];          // coalesced, L1-resident (96KB)
            #pragma unroll
            for (int rr = 0; rr < 8; rr++)
                acc[rr] = fmaf(h_s[rbase + rr][k], w, acc[rr]);
        }
        float bb = b2[c];
        float e0 = eta[0];
        #pragma unroll
        for (int rr = 0; rr < 8; rr++)
            p_s[rbase + rr][c] = (acc[rr] + bb) * e0;
    }
    __syncthreads();

    // ---- stage 3: circular RQ spline, warp per row, lane = bin ----
    const int wid  = t >> 5;
    const int lane = t & 31;
    const unsigned FULL = 0xffffffffu;

    for (int rr = wid; rr < TILE; rr += NT / 32) {
        int row = row0 + rr;
        if (row >= B) continue;                 // warp-uniform

        float th_in = theta[row];
        float uw = p_s[rr][lane];
        float uh = p_s[rr][NB + lane];
        float ud = p_s[rr][2 * NB + lane] + DERIV_OFF;

        // softmax (with max-subtraction, matching jax.nn.softmax)
        float mw = uw, mh = uh;
        #pragma unroll
        for (int o = 16; o; o >>= 1) {
            mw = fmaxf(mw, __shfl_xor_sync(FULL, mw, o));
            mh = fmaxf(mh, __shfl_xor_sync(FULL, mh, o));
        }
        float ew = expf(uw - mw), eh = expf(uh - mh);
        float sw = ew, sh = eh;
        #pragma unroll
        for (int o = 16; o; o >>= 1) {
            sw += __shfl_xor_sync(FULL, sw, o);
            sh += __shfl_xor_sync(FULL, sh, o);
        }
        float szw = MIN_WH + SIZE_SCALE * (ew / sw);
        float szh = MIN_WH + SIZE_SCALE * (eh / sh);

        // inclusive scan across lanes -> cumulative sizes
        float cw = szw, chs = szh;
        #pragma unroll
        for (int o = 1; o < 32; o <<= 1) {
            float a = __shfl_up_sync(FULL, cw,  o);
            float b = __shfl_up_sync(FULL, chs, o);
            if (lane >= o) { cw += a; chs += b; }
        }

        // knot positions: lane j holds knot (j+1); knot 32 forced to 2*pi, knot 0 = 0
        float kw = (lane == 31) ? TWO_PI_F : TWO_PI_F * cw;
        float kh = (lane == 31) ? TWO_PI_F : TWO_PI_F * chs;

        // bin search via ballot: count knots (1..32) <= theta
        unsigned bal = __ballot_sync(FULL, th_in >= kw);
        int bin = __popc(bal);
        if (bin > NB - 1) bin = NB - 1;
        int lo = (bin > 0) ? bin - 1 : 0;

        float cw_hi = __shfl_sync(FULL, kw, bin);
        float cw_lo = __shfl_sync(FULL, kw, lo);
        float ch_hi = __shfl_sync(FULL, kh, bin);
        float ch_lo = __shfl_sync(FULL, kh, lo);
        if (bin == 0) { cw_lo = 0.0f; ch_lo = 0.0f; }

        float in_w = cw_hi - cw_lo;
        float in_h = ch_hi - ch_lo;

        // derivatives (circular: deriv[32] == deriv[0])
        float dsp  = MIN_D + softplus_f(ud);
        float d_k  = __shfl_sync(FULL, dsp, bin);
        float d_k1 = __shfl_sync(FULL, dsp, (bin + 1) & 31);

        float delta = in_h / in_w;
        float th    = (th_in - cw_lo) / in_w;
        float om    = th * (1.0f - th);
        float den   = delta + (d_k1 + d_k - 2.0f * delta) * om;
        float num   = in_h * (delta * th * th + d_k * om);
        float outv  = ch_lo + num / den;

        float omt = 1.0f - th;
        float dn  = delta * delta * (d_k1 * th * th + 2.0f * delta * om + d_k * omt * omt);
        float lad = logf(dn) - 2.0f * logf(den);

        if (lane == 0) {
            out[row]     = outv;
            out[B + row] = lad;
        }
    }
}

extern "C" void kernel_launch(void* const* d_in, const int* in_sizes, int n_in,
                              void* d_out, int out_size)
{
    const float* theta = (const float*)d_in[0];
    const float* xc    = (const float*)d_in[1];
    const float* W1    = (const float*)d_in[2];
    const float* b1    = (const float*)d_in[3];
    const float* W2    = (const float*)d_in[4];
    const float* b2    = (const float*)d_in[5];
    const float* eta   = (const float*)d_in[6];
    float* out = (float*)d_out;

    int B = in_sizes[0];                 // theta is (B, 1)
    int grid = (B + TILE - 1) / TILE;
    cyl_flow_kernel<<<grid, NT>>>(theta, xc, W1, b1, W2, b2, eta, out, B);
}

// round 4
// speedup vs baseline: 1.7662x; 1.7662x over previous
#include <cuda_runtime.h>
#include <math.h>

// Problem constants
#define NB    32
#define NFEAT 64
#define NH    256
#define NP    96
#define TILE  16
#define NT    256
#define XPAD  20      // padded row stride (floats): 80B, 16B-aligned, conflict-free stores

#define TWO_PI_F   6.2831853071795864769f
#define MIN_WH     1e-3f
#define MIN_D      1e-3f
#define DERIV_OFF  0.5413248546129181f   // log(e-1)
#define SIZE_SCALE (1.0f - 1e-3f * 32.0f)

__device__ __forceinline__ float softplus_f(float x) {
    return (x > 0.0f) ? (x + log1pf(expf(-x))) : log1pf(expf(x));
}

// ---- packed f32x2 helpers (sm_103a) ----
__device__ __forceinline__ unsigned long long pack2(float v) {
    unsigned long long r;
    asm("mov.b64 %0, {%1, %1};" : "=l"(r) : "f"(v));
    return r;
}
__device__ __forceinline__ void ffma2(unsigned long long &d,
                                      unsigned long long a,
                                      unsigned long long b) {
    asm("fma.rn.f32x2 %0, %1, %2, %0;" : "+l"(d) : "l"(a), "l"(b));
}
__device__ __forceinline__ float2 unpack2(unsigned long long v) {
    float2 f;
    asm("mov.b64 {%0, %1}, %2;" : "=f"(f.x), "=f"(f.y) : "l"(v));
    return f;
}

__global__ __launch_bounds__(NT)
void cyl_flow_kernel(const float* __restrict__ theta,
                     const float* __restrict__ xc,
                     const float* __restrict__ W1,
                     const float* __restrict__ b1,
                     const float* __restrict__ W2,
                     const float* __restrict__ b2,
                     const float* __restrict__ eta,
                     float* __restrict__ out,
                     int B)
{
    __shared__ float x_t[NFEAT * XPAD];   // x_t[k*XPAD + r], 5.1 KB (transposed)
    __shared__ float h_t[NH * XPAD];      // h_t[k*XPAD + r], 20.5 KB (transposed)
    __shared__ float part[TILE][NP];      // stage-2 k-half partials, 6 KB
    __shared__ float p_s[TILE][NP];       // final spline params, 6 KB

    const int t    = threadIdx.x;
    const int row0 = blockIdx.x * TILE;

    // ---- load x tile, transposed (coalesced LDG; 4-way-conflict STS, one-time) ----
    #pragma unroll
    for (int i = t; i < TILE * NFEAT; i += NT) {
        int r = i >> 6, k = i & 63;
        int row = row0 + r;
        x_t[k * XPAD + r] = (row < B) ? xc[row * NFEAT + k] : 0.0f;
    }
    __syncthreads();

    // ---- stage 1: h = relu(x @ W1 + b1); thread t = hidden column, 16 rows packed f32x2 ----
    {
        const int c = t;
        unsigned long long acc[8];
        #pragma unroll
        for (int j = 0; j < 8; j++) acc[j] = 0ULL;

        const float* w1p = W1 + c;
        #pragma unroll 8
        for (int k = 0; k < NFEAT; k++) {
            unsigned long long wp = pack2(w1p[k * NH]);          // coalesced LDG, L1-hot
            const ulonglong2* xp = (const ulonglong2*)(x_t + k * XPAD);
            ulonglong2 a0 = xp[0], a1 = xp[1], a2 = xp[2], a3 = xp[3];  // broadcast LDS.128
            ffma2(acc[0], a0.x, wp); ffma2(acc[1], a0.y, wp);
            ffma2(acc[2], a1.x, wp); ffma2(acc[3], a1.y, wp);
            ffma2(acc[4], a2.x, wp); ffma2(acc[5], a2.y, wp);
            ffma2(acc[6], a3.x, wp); ffma2(acc[7], a3.y, wp);
        }
        float bb = b1[c];
        float* hp = h_t + c * XPAD;
        #pragma unroll
        for (int q = 0; q < 4; q++) {                 // 4× STS.128, conflict-free (80B stride)
            float2 f0 = unpack2(acc[2 * q]);
            float2 f1 = unpack2(acc[2 * q + 1]);
            float4 hv;
            hv.x = fmaxf(f0.x + bb, 0.0f);
            hv.y = fmaxf(f0.y + bb, 0.0f);
            hv.z = fmaxf(f1.x + bb, 0.0f);
            hv.w = fmaxf(f1.y + bb, 0.0f);
            *(float4*)(hp + 4 * q) = hv;
        }
    }
    __syncthreads();

    // ---- stage 2: params = (h @ W2 + b2) * eta, k split 2-way over 192 threads ----
    unsigned long long acc2[8];
    #pragma unroll
    for (int j = 0; j < 8; j++) acc2[j] = 0ULL;

    const int g = (t >= 96) ? 1 : 0;
    const int c2 = t - g * 96;

    if (t < 192) {
        const float* w2p = W2 + c2;
        const int k0 = g * (NH / 2);
        #pragma unroll 8
        for (int kk = 0; kk < NH / 2; kk++) {
            int k = k0 + kk;
            unsigned long long wp = pack2(w2p[k * NP]);          // coalesced per warp
            const ulonglong2* hp = (const ulonglong2*)(h_t + k * XPAD);
            ulonglong2 a0 = hp[0], a1 = hp[1], a2 = hp[2], a3 = hp[3];  // broadcast LDS.128
            ffma2(acc2[0], a0.x, wp); ffma2(acc2[1], a0.y, wp);
            ffma2(acc2[2], a1.x, wp); ffma2(acc2[3], a1.y, wp);
            ffma2(acc2[4], a2.x, wp); ffma2(acc2[5], a2.y, wp);
            ffma2(acc2[6], a3.x, wp); ffma2(acc2[7], a3.y, wp);
        }
        if (g) {
            #pragma unroll
            for (int j = 0; j < 8; j++) {
                float2 f = unpack2(acc2[j]);
                part[2 * j][c2]     = f.x;       // consecutive c -> conflict-free
                part[2 * j + 1][c2] = f.y;
            }
        }
    }
    __syncthreads();

    if (t < 96) {
        float bb = b2[t];
        float e0 = eta[0];
        #pragma unroll
        for (int j = 0; j < 8; j++) {
            float2 f = unpack2(acc2[j]);
            p_s[2 * j][t]     = (f.x + part[2 * j][t] + bb) * e0;
            p_s[2 * j + 1][t] = (f.y + part[2 * j + 1][t] + bb) * e0;
        }
    }
    __syncthreads();

    // ---- stage 3: circular RQ spline, warp per row, lane = bin ----
    const int wid  = t >> 5;
    const int lane = t & 31;
    const unsigned FULL = 0xffffffffu;

    for (int rr = wid; rr < TILE; rr += NT / 32) {
        int row = row0 + rr;
        if (row >= B) continue;                 // warp-uniform

        float th_in = theta[row];
        float uw = p_s[rr][lane];
        float uh = p_s[rr][NB + lane];
        float ud = p_s[rr][2 * NB + lane] + DERIV_OFF;

        // softmax (max-subtracted, matching jax.nn.softmax)
        float mw = uw, mh = uh;
        #pragma unroll
        for (int o = 16; o; o >>= 1) {
            mw = fmaxf(mw, __shfl_xor_sync(FULL, mw, o));
            mh = fmaxf(mh, __shfl_xor_sync(FULL, mh, o));
        }
        float ew = expf(uw - mw), eh = expf(uh - mh);
        float sw = ew, sh = eh;
        #pragma unroll
        for (int o = 16; o; o >>= 1) {
            sw += __shfl_xor_sync(FULL, sw, o);
            sh += __shfl_xor_sync(FULL, sh, o);
        }
        float szw = MIN_WH + SIZE_SCALE * (ew / sw);
        float szh = MIN_WH + SIZE_SCALE * (eh / sh);

        // inclusive scan -> cumulative sizes
        float cw = szw, chs = szh;
        #pragma unroll
        for (int o = 1; o < 32; o <<= 1) {
            float a = __shfl_up_sync(FULL, cw,  o);
            float b = __shfl_up_sync(FULL, chs, o);
            if (lane >= o) { cw += a; chs += b; }
        }

        // knots: lane j holds knot (j+1); knot 32 forced to 2*pi, knot 0 = 0
        float kw = (lane == 31) ? TWO_PI_F : TWO_PI_F * cw;
        float kh = (lane == 31) ? TWO_PI_F : TWO_PI_F * chs;

        unsigned bal = __ballot_sync(FULL, th_in >= kw);
        int bin = __popc(bal);
        if (bin > NB - 1) bin = NB - 1;
        int lo = (bin > 0) ? bin - 1 : 0;

        float cw_hi = __shfl_sync(FULL, kw, bin);
        float cw_lo = __shfl_sync(FULL, kw, lo);
        float ch_hi = __shfl_sync(FULL, kh, bin);
        float ch_lo = __shfl_sync(FULL, kh, lo);
        if (bin == 0) { cw_lo = 0.0f; ch_lo = 0.0f; }

        float in_w = cw_hi - cw_lo;
        float in_h = ch_hi - ch_lo;

        float dsp  = MIN_D + softplus_f(ud);
        float d_k  = __shfl_sync(FULL, dsp, bin);
        float d_k1 = __shfl_sync(FULL, dsp, (bin + 1) & 31);

        float delta = in_h / in_w;
        float th    = (th_in - cw_lo) / in_w;
        float om    = th * (1.0f - th);
        float den   = delta + (d_k1 + d_k - 2.0f * delta) * om;
        float num   = in_h * (delta * th * th + d_k * om);
        float outv  = ch_lo + num / den;

        float omt = 1.0f - th;
        float dn  = delta * delta * (d_k1 * th * th + 2.0f * delta * om + d_k * omt * omt);
        float lad = logf(dn) - 2.0f * logf(den);

        if (lane == 0) {
            out[row]     = outv;
            out[B + row] = lad;
        }
    }
}

extern "C" void kernel_launch(void* const* d_in, const int* in_sizes, int n_in,
                              void* d_out, int out_size)
{
    const float* theta = (const float*)d_in[0];
    const float* xc    = (const float*)d_in[1];
    const float* W1    = (const float*)d_in[2];
    const float* b1    = (const float*)d_in[3];
    const float* W2    = (const float*)d_in[4];
    const float* b2    = (const float*)d_in[5];
    const float* eta   = (const float*)d_in[6];
    float* out = (float*)d_out;

    int B = in_sizes[0];
    int grid = (B + TILE - 1) / TILE;
    cyl_flow_kernel<<<grid, NT>>>(theta, xc, W1, b1, W2, b2, eta, out, B);
}